// round 2
// baseline (speedup 1.0000x reference)
#include <cuda_runtime.h>

// param_distance: K=8, B=32, N=4096, D=64 ; BN = 131072
// out[row] = agg[argmin_k sum_d |t[row,d]-agg[k,row,d]|, row, 0]
//
// Half-warp-per-row: lane holds float4 (d = 4*sub .. 4*sub+3), 16 lanes per row,
// each warp handles 2 rows. All loads are LDG.128 (__ldcs, evict-first streaming).
// MLP_p1 = 18 LDG.128 per warp (4608 B in flight). Butterfly over 16 lanes.

__global__ __launch_bounds__(256)
void param_distance_kernel(const float* __restrict__ tensor,
                           const float* __restrict__ agg,
                           float* __restrict__ out,
                           int BN)
{
    const int warpid = blockIdx.x * (blockDim.x >> 5) + (threadIdx.x >> 5);
    const int lane   = threadIdx.x & 31;
    const int half   = lane >> 4;      // which row of the pair
    const int sub    = lane & 15;      // lane within half-warp
    const int row    = warpid * 2 + half;
    if (row >= BN) return;

    const size_t rbase   = (size_t)row * 64 + (size_t)sub * 4;
    const size_t kstride = (size_t)BN * 64;

    // 128-bit streaming loads; each half-warp covers a contiguous 256B row slice
    const float4 tv = __ldcs(reinterpret_cast<const float4*>(tensor + rbase));

    float4 av[8];
#pragma unroll
    for (int k = 0; k < 8; ++k)
        av[k] = __ldcs(reinterpret_cast<const float4*>(agg + (size_t)k * kstride + rbase));

    float best  = 3.402823466e38f;
    float bestv = 0.0f;
    const int grp0 = half << 4;        // base lane of this half-warp (0 or 16)

#pragma unroll
    for (int k = 0; k < 8; ++k) {
        float p = fabsf(tv.x - av[k].x) + fabsf(tv.y - av[k].y)
                + fabsf(tv.z - av[k].z) + fabsf(tv.w - av[k].w);
        // butterfly within the 16-lane group (xor offsets stay inside the group)
#pragma unroll
        for (int off = 8; off > 0; off >>= 1)
            p += __shfl_xor_sync(0xFFFFFFFFu, p, off);
        // feature element 0 of candidate k lives in the group's base lane
        const float a0 = __shfl_sync(0xFFFFFFFFu, av[k].x, grp0);
        if (p < best) { best = p; bestv = a0; }   // strict < => first-index tie-break
    }

    if (sub == 0) out[row] = bestv;
}

extern "C" void kernel_launch(void* const* d_in, const int* in_sizes, int n_in,
                              void* d_out, int out_size)
{
    const float* tensor = (const float*)d_in[0];   // [B, N, D] fp32
    const float* agg    = (const float*)d_in[1];   // [K, B, N, D] fp32
    float* out          = (float*)d_out;           // [1, B, N, 1] fp32

    const int D  = 64;
    const int BN = in_sizes[0] / D;                // 131072

    const int threads = 256;                       // 8 warps -> 16 rows per block
    const int rows_per_block = (threads / 32) * 2;
    const int blocks = (BN + rows_per_block - 1) / rows_per_block;

    param_distance_kernel<<<blocks, threads>>>(tensor, agg, out, BN);
}

// round 3
// speedup vs baseline: 1.0604x; 1.0604x over previous
#include <cuda_runtime.h>

// param_distance: K=8, B=32, N=4096, D=64 ; BN = 131072
// out[row] = agg[argmin_k sum_d |t[row,d]-agg[k,row,d]|, row, 0]
//
// Warp-per-row (R1 memory structure: float2 per lane, 9 batched LDG.64).
// Reduction: multi-value split butterfly (9 SHFLs for all 8 candidate sums)
// + 3-stage argmin butterfly with explicit index tie-break (6 SHFLs).

__global__ __launch_bounds__(256, 8)
void param_distance_kernel(const float* __restrict__ tensor,
                           const float* __restrict__ agg,
                           float* __restrict__ out,
                           int BN)
{
    const int row  = blockIdx.x * (blockDim.x >> 5) + (threadIdx.x >> 5);
    const int lane = threadIdx.x & 31;
    if (row >= BN) return;

    const size_t rbase   = (size_t)row * 64;
    const size_t kstride = (size_t)BN * 64;

    const float2 tv = *reinterpret_cast<const float2*>(tensor + rbase + lane * 2);

    float2 av[8];
#pragma unroll
    for (int k = 0; k < 8; ++k)
        av[k] = *reinterpret_cast<const float2*>(agg + (size_t)k * kstride + rbase + lane * 2);

    float p[8];
#pragma unroll
    for (int k = 0; k < 8; ++k)
        p[k] = fabsf(tv.x - av[k].x) + fabsf(tv.y - av[k].y);

    // ---- split butterfly: distribute the 8 sums across lane groups ----
    // stage 1 (xor 16): low half keeps k0..3, high half keeps k4..7
    const bool hi16 = (lane & 16) != 0;
    float q[4];
#pragma unroll
    for (int j = 0; j < 4; ++j) {
        float send = hi16 ? p[j] : p[j + 4];
        float recv = __shfl_xor_sync(0xFFFFFFFFu, send, 16);
        q[j] = (hi16 ? p[j + 4] : p[j]) + recv;
    }
    // stage 2 (xor 8)
    const bool hi8 = (lane & 8) != 0;
    float r[2];
#pragma unroll
    for (int j = 0; j < 2; ++j) {
        float send = hi8 ? q[j] : q[j + 2];
        float recv = __shfl_xor_sync(0xFFFFFFFFu, send, 8);
        r[j] = (hi8 ? q[j + 2] : q[j]) + recv;
    }
    // stage 3 (xor 4)
    const bool hi4 = (lane & 4) != 0;
    {
        float send = hi4 ? r[0] : r[1];
        float recv = __shfl_xor_sync(0xFFFFFFFFu, send, 4);
        r[0] = (hi4 ? r[1] : r[0]) + recv;
    }
    float s = r[0];
    // finish the sum within each 4-lane replica group
    s += __shfl_xor_sync(0xFFFFFFFFu, s, 2);
    s += __shfl_xor_sync(0xFFFFFFFFu, s, 1);

    // lane's candidate index
    int myk = ((lane >> 4) & 1) * 4 + ((lane >> 3) & 1) * 2 + ((lane >> 2) & 1);

    // ---- argmin butterfly over offsets 4,8,16 (replicas consistent) ----
    float bv = s;
    int   bk = myk;
#pragma unroll
    for (int off = 4; off <= 16; off <<= 1) {
        float ov = __shfl_xor_sync(0xFFFFFFFFu, bv, off);
        int   ok = __shfl_xor_sync(0xFFFFFFFFu, bk, off);
        if (ov < bv || (ov == bv && ok < bk)) { bv = ov; bk = ok; }
    }
    // all lanes now agree on bk (first-index tie-break preserved)

    // feature element 0 of candidate bk lives in lane 0's av[bk].x
    float a0 = av[0].x;
    a0 = (bk == 1) ? av[1].x : a0;
    a0 = (bk == 2) ? av[2].x : a0;
    a0 = (bk == 3) ? av[3].x : a0;
    a0 = (bk == 4) ? av[4].x : a0;
    a0 = (bk == 5) ? av[5].x : a0;
    a0 = (bk == 6) ? av[6].x : a0;
    a0 = (bk == 7) ? av[7].x : a0;

    if (lane == 0) out[row] = a0;
}

extern "C" void kernel_launch(void* const* d_in, const int* in_sizes, int n_in,
                              void* d_out, int out_size)
{
    const float* tensor = (const float*)d_in[0];   // [B, N, D] fp32
    const float* agg    = (const float*)d_in[1];   // [K, B, N, D] fp32
    float* out          = (float*)d_out;           // [1, B, N, 1] fp32

    const int D  = 64;
    const int BN = in_sizes[0] / D;                // 131072

    const int threads = 256;                       // 8 warps -> 8 rows per block
    const int rows_per_block = threads / 32;
    const int blocks = (BN + rows_per_block - 1) / rows_per_block;

    param_distance_kernel<<<blocks, threads>>>(tensor, agg, out, BN);
}